// round 1
// baseline (speedup 1.0000x reference)
#include <cuda_runtime.h>

#define ALPHA 0.2f
#define BN_EPS 1e-5f

typedef unsigned long long u64;

__device__ __forceinline__ u64 ffma2(u64 a, u64 b, u64 c){
    u64 d; asm("fma.rn.f32x2 %0, %1, %2, %3;" : "=l"(d) : "l"(a), "l"(b), "l"(c)); return d;
}
__device__ __forceinline__ float2 upk(u64 v){
    float2 r; asm("mov.b64 {%0, %1}, %2;" : "=f"(r.x), "=f"(r.y) : "l"(v)); return r;
}
__device__ __forceinline__ u64 pk(float lo, float hi){
    u64 r; asm("mov.b64 %0, {%1, %2};" : "=l"(r) : "f"(lo), "f"(hi)); return r;
}
__device__ __forceinline__ float hsum(u64 v){ float2 t = upk(v); return t.x + t.y; }

// ---- shared memory layout (float offsets) ----
#define WT1_OFF   0                 // 64 rows x 132 (125 used, pad 0) = 8448
#define WT2_OFF   8448              // packed float4: [16][32] = 2048 floats
#define WL2_OFF   10496             // packed float2: [13][5][32] = 4160 floats
#define A11_OFF   14656             // 64
#define A21_OFF   14720             // 64
#define A12_OFF   14784             // 32
#define A22_OFF   14816             // 32
#define SC1_OFF   14848             // 5 (pad to 8)
#define SH1_OFF   14856
#define SC2_OFF   14864
#define SH2_OFF   14872
#define BL_OFF    14880             // 13
#define SCR_OFF   14896             // per-warp scratch 1280 floats x 8 warps
#define SMEM_FLOATS (14896 + 8*1280)   // 25136 floats = 100544 bytes

__global__ void __launch_bounds__(256) gat_fused_kernel(
    const float* __restrict__ x,
    const float* __restrict__ Wt1, const float* __restrict__ a11, const float* __restrict__ a21,
    const float* __restrict__ g1,  const float* __restrict__ b1,  const float* __restrict__ m1, const float* __restrict__ v1,
    const float* __restrict__ Wt2, const float* __restrict__ a12, const float* __restrict__ a22,
    const float* __restrict__ g2,  const float* __restrict__ b2,  const float* __restrict__ m2, const float* __restrict__ v2,
    const float* __restrict__ Wl,  const float* __restrict__ bl,
    float* __restrict__ out, int B)
{
    extern __shared__ float sm[];
    const int tid = threadIdx.x;

    // ---------------- block init: stage weights into SMEM ----------------
    for (int i = tid; i < 64*132; i += 256){
        int o = i / 132, f = i - o*132;
        sm[WT1_OFF + i] = (f < 125) ? Wt1[o*125 + f] : 0.f;
    }
    {
        float4* w2p = (float4*)(sm + WT2_OFF);       // [q][p] = Wt2[p][4q..4q+3]
        for (int i = tid; i < 16*32; i += 256){
            int q = i >> 5, p = i & 31;
            const float* s = Wt2 + p*64 + q*4;
            w2p[i] = make_float4(s[0], s[1], s[2], s[3]);
        }
    }
    {
        float2* wlp = (float2*)(sm + WL2_OFF);       // [k][n][l] = (Wl[k][n*64+l], Wl[k][n*64+32+l])
        for (int i = tid; i < 13*5*32; i += 256){
            int k = i / 160, r = i - k*160;
            int n = r >> 5, l = r & 31;
            wlp[i] = make_float2(Wl[k*320 + n*64 + l], Wl[k*320 + n*64 + 32 + l]);
        }
    }
    if (tid < 64){ sm[A11_OFF+tid] = a11[tid]; sm[A21_OFF+tid] = a21[tid]; }
    if (tid < 32){ sm[A12_OFF+tid] = a12[tid]; sm[A22_OFF+tid] = a22[tid]; }
    if (tid < 5){
        float sc = g1[tid] * rsqrtf(v1[tid] + BN_EPS);
        sm[SC1_OFF+tid] = sc; sm[SH1_OFF+tid] = b1[tid] - m1[tid]*sc;
        float s2c = g2[tid] * rsqrtf(v2[tid] + BN_EPS);
        sm[SC2_OFF+tid] = s2c; sm[SH2_OFF+tid] = b2[tid] - m2[tid]*s2c;
    }
    if (tid < 13) sm[BL_OFF+tid] = bl[tid];
    __syncthreads();

    const int wid  = tid >> 5, lane = tid & 31;
    const int b = blockIdx.x * 8 + wid;
    if (b >= B) return;

    float* xs = sm + SCR_OFF + wid*1280;   // per-warp scratch

    // ---------------- load x: xa/xn into [inp][n][128] (pad 125..127 = 0) --------
    const float* xg = x + (size_t)b * 1250;
    for (int i = lane; i < 1250; i += 32){
        int n = i / 250, r = i - n*250;
        int inp = (r >= 125);
        int f = r - inp*125;
        xs[inp*640 + n*128 + f] = xg[i];
    }
    if (lane < 30){
        int inp = lane / 15, r = lane - inp*15;
        int n = r / 3, f = 125 + (r - n*3);
        xs[inp*640 + n*128 + f] = 0.f;
    }
    __syncwarp();

    // ---------------- layer 1 GEMM: H[inp][n][o], lane owns o=lane & o=lane+32 ----
    u64 acc[2][5][2];
    #pragma unroll
    for (int i = 0; i < 2; i++)
        #pragma unroll
        for (int n = 0; n < 5; n++){ acc[i][n][0] = 0ull; acc[i][n][1] = 0ull; }

    const ulonglong2* w0p = (const ulonglong2*)(sm + WT1_OFF + lane*132);
    const ulonglong2* w1p = (const ulonglong2*)(sm + WT1_OFF + (lane+32)*132);
    #pragma unroll 4
    for (int q = 0; q < 32; ++q){          // covers f = 4q .. 4q+3
        ulonglong2 w0 = w0p[q];
        ulonglong2 w1 = w1p[q];
        #pragma unroll
        for (int inp = 0; inp < 2; ++inp)
            #pragma unroll
            for (int n = 0; n < 5; ++n){
                ulonglong2 xv = *(const ulonglong2*)(xs + inp*640 + n*128 + 4*q);
                acc[inp][n][0] = ffma2(xv.x, w0.x, acc[inp][n][0]);
                acc[inp][n][0] = ffma2(xv.y, w0.y, acc[inp][n][0]);
                acc[inp][n][1] = ffma2(xv.x, w1.x, acc[inp][n][1]);
                acc[inp][n][1] = ffma2(xv.y, w1.y, acc[inp][n][1]);
            }
    }
    float H[2][5][2];
    #pragma unroll
    for (int inp = 0; inp < 2; inp++)
        #pragma unroll
        for (int n = 0; n < 5; n++){
            H[inp][n][0] = hsum(acc[inp][n][0]);
            H[inp][n][1] = hsum(acc[inp][n][1]);
        }

    // ---------------- layer 1 scores: s1 = H.a11, s2 = H.a21 (warp reduce) -------
    float s1[2][5], s2[2][5];
    {
        float a110 = sm[A11_OFF+lane], a111 = sm[A11_OFF+32+lane];
        float a210 = sm[A21_OFF+lane], a211 = sm[A21_OFF+32+lane];
        #pragma unroll
        for (int inp = 0; inp < 2; inp++)
            #pragma unroll
            for (int n = 0; n < 5; n++){
                float p1 = H[inp][n][0]*a110 + H[inp][n][1]*a111;
                float p2 = H[inp][n][0]*a210 + H[inp][n][1]*a211;
                #pragma unroll
                for (int d = 16; d > 0; d >>= 1){
                    p1 += __shfl_xor_sync(0xffffffffu, p1, d);
                    p2 += __shfl_xor_sync(0xffffffffu, p2, d);
                }
                s1[inp][n] = p1; s2[inp][n] = p2;
            }
    }

    // ---------------- layer 1 softmax over i (column-normalized) -----------------
    float* abuf = xs;      // reuse scratch front: attn[inp*32 + i*5 + j]
    {
        int g = lane / 5, j = lane - g*5;
        if (lane < 10){
            float t1[5], t2[5];
            #pragma unroll
            for (int i = 0; i < 5; i++){
                t1[i] = g ? s1[1][i] : s1[0][i];
                t2[i] = g ? s2[1][i] : s2[0][i];
            }
            float t2j = (j==0)?t2[0]:(j==1)?t2[1]:(j==2)?t2[2]:(j==3)?t2[3]:t2[4];
            float ex[5], cs = 0.f;
            #pragma unroll
            for (int i = 0; i < 5; i++){
                float e = t1[i] + t2j;
                e = (e > 0.f) ? e : ALPHA*e;
                ex[i] = __expf(e);
                cs += ex[i];
            }
            float rc = __fdividef(1.f, cs);
            #pragma unroll
            for (int i = 0; i < 5; i++) abuf[g*32 + i*5 + j] = ex[i]*rc;
        }
    }
    __syncwarp();

    // ---------------- layer 1 apply + BN1 + ReLU -> h2s ----------------
    float O[2][5][2];
    #pragma unroll
    for (int inp = 0; inp < 2; inp++)
        #pragma unroll
        for (int i = 0; i < 5; i++){ O[inp][i][0] = 0.f; O[inp][i][1] = 0.f; }
    #pragma unroll
    for (int inp = 0; inp < 2; inp++)
        #pragma unroll
        for (int i = 0; i < 5; i++)
            #pragma unroll
            for (int j = 0; j < 5; j++){
                float a = abuf[inp*32 + i*5 + j];
                O[inp][i][0] += a * H[inp][j][0];
                O[inp][i][1] += a * H[inp][j][1];
            }
    float* h2s = xs + 256;   // [inp][n][64]
    #pragma unroll
    for (int inp = 0; inp < 2; inp++)
        #pragma unroll
        for (int n = 0; n < 5; n++){
            float sc = sm[SC1_OFF+n], sh = sm[SH1_OFF+n];
            h2s[inp*320 + n*64 + lane]      = fmaxf(0.f, O[inp][n][0]*sc + sh);
            h2s[inp*320 + n*64 + 32 + lane] = fmaxf(0.f, O[inp][n][1]*sc + sh);
        }
    __syncwarp();

    // ---------------- layer 2 GEMM: hh[inp][n] at p = lane ----------------
    u64 acc2[2][5];
    #pragma unroll
    for (int inp = 0; inp < 2; inp++)
        #pragma unroll
        for (int n = 0; n < 5; n++) acc2[inp][n] = 0ull;
    const ulonglong2* w2p = (const ulonglong2*)(sm + WT2_OFF);
    #pragma unroll 4
    for (int q = 0; q < 16; ++q){
        ulonglong2 w = w2p[q*32 + lane];
        #pragma unroll
        for (int inp = 0; inp < 2; ++inp)
            #pragma unroll
            for (int n = 0; n < 5; ++n){
                ulonglong2 xv = *(const ulonglong2*)(h2s + inp*320 + n*64 + 4*q);
                acc2[inp][n] = ffma2(xv.x, w.x, acc2[inp][n]);
                acc2[inp][n] = ffma2(xv.y, w.y, acc2[inp][n]);
            }
    }
    float hh[2][5];
    #pragma unroll
    for (int inp = 0; inp < 2; inp++)
        #pragma unroll
        for (int n = 0; n < 5; n++) hh[inp][n] = hsum(acc2[inp][n]);

    // ---------------- layer 2 scores ----------------
    float uu[2][5], wv[2][5];
    {
        float a12l = sm[A12_OFF+lane], a22l = sm[A22_OFF+lane];
        #pragma unroll
        for (int inp = 0; inp < 2; inp++)
            #pragma unroll
            for (int n = 0; n < 5; n++){
                float pu = hh[inp][n]*a12l;
                float pw = hh[inp][n]*a22l;
                #pragma unroll
                for (int d = 16; d > 0; d >>= 1){
                    pu += __shfl_xor_sync(0xffffffffu, pu, d);
                    pw += __shfl_xor_sync(0xffffffffu, pw, d);
                }
                uu[inp][n] = pu; wv[inp][n] = pw;
            }
    }

    // ---------------- layer 2 softmax: g=0 -> ya (h1=hh[0], s2 from hh[1]); g=1 -> yn
    {
        int g = lane / 5, j = lane - g*5;
        if (lane < 10){
            float t1[5], t2[5];
            #pragma unroll
            for (int i = 0; i < 5; i++){
                t1[i] = g ? uu[1][i] : uu[0][i];
                t2[i] = g ? wv[0][i] : wv[1][i];
            }
            float t2j = (j==0)?t2[0]:(j==1)?t2[1]:(j==2)?t2[2]:(j==3)?t2[3]:t2[4];
            float ex[5], cs = 0.f;
            #pragma unroll
            for (int i = 0; i < 5; i++){
                float e = t1[i] + t2j;
                e = (e > 0.f) ? e : ALPHA*e;
                ex[i] = __expf(e);
                cs += ex[i];
            }
            float rc = __fdividef(1.f, cs);
            #pragma unroll
            for (int i = 0; i < 5; i++) abuf[g*32 + i*5 + j] = ex[i]*rc;
        }
    }
    __syncwarp();

    // ---------------- layer 2 apply + BN2 + ReLU ----------------
    float O2[2][5];
    #pragma unroll
    for (int g = 0; g < 2; g++)
        #pragma unroll
        for (int i = 0; i < 5; i++) O2[g][i] = 0.f;
    #pragma unroll
    for (int g = 0; g < 2; g++)
        #pragma unroll
        for (int i = 0; i < 5; i++)
            #pragma unroll
            for (int j = 0; j < 5; j++){
                float a = abuf[g*32 + i*5 + j];
                O2[g][i] += a * hh[g][j];
            }
    float y2[2][5];
    #pragma unroll
    for (int g = 0; g < 2; g++)
        #pragma unroll
        for (int n = 0; n < 5; n++)
            y2[g][n] = fmaxf(0.f, O2[g][n]*sm[SC2_OFF+n] + sm[SH2_OFF+n]);

    // ---------------- final linear (13 outputs) ----------------
    u64 f2[5];
    #pragma unroll
    for (int n = 0; n < 5; n++) f2[n] = pk(y2[0][n], y2[1][n]);   // (ya, yn) pair at feat c = n*64 + lane(+32)
    const u64* wlp = (const u64*)(sm + WL2_OFF);
    float r[13];
    #pragma unroll
    for (int k = 0; k < 13; k++){
        u64 a = 0ull;
        #pragma unroll
        for (int n = 0; n < 5; n++)
            a = ffma2(f2[n], wlp[k*160 + n*32 + lane], a);
        float rk = hsum(a);
        #pragma unroll
        for (int d = 16; d > 0; d >>= 1) rk += __shfl_xor_sync(0xffffffffu, rk, d);
        r[k] = rk;
    }
    if (lane == 0){
        float* op = out + (size_t)b * 13;
        #pragma unroll
        for (int k = 0; k < 13; k++) op[k] = r[k] + sm[BL_OFF+k];
    }
}

extern "C" void kernel_launch(void* const* d_in, const int* in_sizes, int n_in,
                              void* d_out, int out_size)
{
    const float* x   = (const float*)d_in[0];
    const float* Wt1 = (const float*)d_in[1];
    const float* a11 = (const float*)d_in[2];
    const float* a21 = (const float*)d_in[3];
    const float* g1  = (const float*)d_in[4];
    const float* b1  = (const float*)d_in[5];
    const float* m1  = (const float*)d_in[6];
    const float* v1  = (const float*)d_in[7];
    const float* Wt2 = (const float*)d_in[8];
    const float* a12 = (const float*)d_in[9];
    const float* a22 = (const float*)d_in[10];
    const float* g2  = (const float*)d_in[11];
    const float* b2  = (const float*)d_in[12];
    const float* m2  = (const float*)d_in[13];
    const float* v2  = (const float*)d_in[14];
    const float* Wl  = (const float*)d_in[15];
    const float* bl  = (const float*)d_in[16];

    int B = in_sizes[0] / 1250;
    size_t smem_bytes = (size_t)SMEM_FLOATS * sizeof(float);
    cudaFuncSetAttribute(gat_fused_kernel,
                         cudaFuncAttributeMaxDynamicSharedMemorySize, (int)smem_bytes);

    dim3 grid((B + 7) / 8);
    gat_fused_kernel<<<grid, 256, smem_bytes>>>(
        x, Wt1, a11, a21, g1, b1, m1, v1,
        Wt2, a12, a22, g2, b2, m2, v2, Wl, bl,
        (float*)d_out, B);
}

// round 3
// speedup vs baseline: 1.3169x; 1.3169x over previous
#include <cuda_runtime.h>

#define ALPHA 0.2f
#define BN_EPS 1e-5f
#define THREADS 768
#define WARPS 24

typedef unsigned long long u64;

__device__ __forceinline__ u64 ffma2(u64 a, u64 b, u64 c){
    u64 d; asm("fma.rn.f32x2 %0, %1, %2, %3;" : "=l"(d) : "l"(a), "l"(b), "l"(c)); return d;
}
__device__ __forceinline__ float2 upk(u64 v){
    float2 r; asm("mov.b64 {%0, %1}, %2;" : "=f"(r.x), "=f"(r.y) : "l"(v)); return r;
}
__device__ __forceinline__ u64 pk(float lo, float hi){
    u64 r; asm("mov.b64 %0, {%1, %2};" : "=l"(r) : "f"(lo), "f"(hi)); return r;
}
__device__ __forceinline__ float hsum(u64 v){ float2 t = upk(v); return t.x + t.y; }
__device__ __forceinline__ float wsum(float v){
    #pragma unroll
    for (int d = 16; d > 0; d >>= 1) v += __shfl_xor_sync(0xffffffffu, v, d);
    return v;
}

// ---- shared memory layout (float offsets) ----
#define WT1_OFF   0                 // 64 rows x 132 (125 used, pad 0) = 8448
#define WT2_OFF   8448              // packed float4: [16][32] = 2048 floats
#define WL2_OFF   10496             // packed float2: [13][5][32] = 4160 floats
#define A11_OFF   14656             // 64
#define A21_OFF   14720             // 64
#define A12_OFF   14784             // 32
#define A22_OFF   14816             // 32
#define SC1_OFF   14848
#define SH1_OFF   14856
#define SC2_OFF   14864
#define SH2_OFF   14872
#define BL_OFF    14880             // 13 (pad 16)
#define SCR_OFF   14896             // per-warp scratch 1344 floats
#define WSCR      1344
#define SMEM_FLOATS (SCR_OFF + WARPS*WSCR)   // 47152 floats = 188608 bytes

__global__ void __launch_bounds__(THREADS, 1) gat_fused_kernel(
    const float* __restrict__ x,
    const float* __restrict__ Wt1, const float* __restrict__ a11, const float* __restrict__ a21,
    const float* __restrict__ g1,  const float* __restrict__ b1,  const float* __restrict__ m1, const float* __restrict__ v1,
    const float* __restrict__ Wt2, const float* __restrict__ a12, const float* __restrict__ a22,
    const float* __restrict__ g2,  const float* __restrict__ b2,  const float* __restrict__ m2, const float* __restrict__ v2,
    const float* __restrict__ Wl,  const float* __restrict__ bl,
    float* __restrict__ out, int B)
{
    extern __shared__ float sm[];
    const int tid = threadIdx.x;

    // ---------------- block init: stage weights into SMEM ----------------
    for (int i = tid; i < 64*132; i += THREADS){
        int o = i / 132, f = i - o*132;
        sm[WT1_OFF + i] = (f < 125) ? Wt1[o*125 + f] : 0.f;
    }
    {
        float4* w2p = (float4*)(sm + WT2_OFF);       // [q][p] = Wt2[p][4q..4q+3]
        for (int i = tid; i < 16*32; i += THREADS){
            int q = i >> 5, p = i & 31;
            const float* s = Wt2 + p*64 + q*4;
            w2p[i] = make_float4(s[0], s[1], s[2], s[3]);
        }
    }
    {
        float2* wlp = (float2*)(sm + WL2_OFF);       // [k][n][l]
        for (int i = tid; i < 13*5*32; i += THREADS){
            int k = i / 160, r = i - k*160;
            int n = r >> 5, l = r & 31;
            wlp[i] = make_float2(Wl[k*320 + n*64 + l], Wl[k*320 + n*64 + 32 + l]);
        }
    }
    if (tid < 64){ sm[A11_OFF+tid] = a11[tid]; sm[A21_OFF+tid] = a21[tid]; }
    if (tid < 32){ sm[A12_OFF+tid] = a12[tid]; sm[A22_OFF+tid] = a22[tid]; }
    if (tid < 5){
        float sc = g1[tid] * rsqrtf(v1[tid] + BN_EPS);
        sm[SC1_OFF+tid] = sc; sm[SH1_OFF+tid] = b1[tid] - m1[tid]*sc;
        float s2c = g2[tid] * rsqrtf(v2[tid] + BN_EPS);
        sm[SC2_OFF+tid] = s2c; sm[SH2_OFF+tid] = b2[tid] - m2[tid]*s2c;
    }
    if (tid < 13) sm[BL_OFF+tid] = bl[tid];
    __syncthreads();

    const int wid  = tid >> 5, lane = tid & 31;
    const int b = blockIdx.x * WARPS + wid;
    if (b >= B) return;

    float* ws = sm + SCR_OFF + wid*WSCR;

    // ---------------- load x: [inp][n][128] (pad 125..127 = 0), no divisions ----
    const float* xg = x + (size_t)b * 1250;
    #pragma unroll
    for (int n = 0; n < 5; n++)
        #pragma unroll
        for (int inp = 0; inp < 2; inp++){
            const float* src = xg + n*250 + inp*125;
            float* dst = ws + inp*640 + n*128;
            dst[lane]      = src[lane];
            dst[lane+32]   = src[lane+32];
            dst[lane+64]   = src[lane+64];
            dst[lane+96]   = (lane+96 < 125) ? src[lane+96] : 0.f;
        }
    __syncwarp();

    // ---------------- layer 1 GEMM: lane owns o=lane & o=lane+32 ----
    u64 acc[2][5][2];
    #pragma unroll
    for (int i = 0; i < 2; i++)
        #pragma unroll
        for (int n = 0; n < 5; n++){ acc[i][n][0] = 0ull; acc[i][n][1] = 0ull; }

    const ulonglong2* w0p = (const ulonglong2*)(sm + WT1_OFF + lane*132);
    const ulonglong2* w1p = (const ulonglong2*)(sm + WT1_OFF + (lane+32)*132);
    #pragma unroll 4
    for (int q = 0; q < 32; ++q){
        ulonglong2 w0 = w0p[q];
        ulonglong2 w1 = w1p[q];
        #pragma unroll
        for (int inp = 0; inp < 2; ++inp)
            #pragma unroll
            for (int n = 0; n < 5; ++n){
                ulonglong2 xv = *(const ulonglong2*)(ws + inp*640 + n*128 + 4*q);
                acc[inp][n][0] = ffma2(xv.x, w0.x, acc[inp][n][0]);
                acc[inp][n][0] = ffma2(xv.y, w0.y, acc[inp][n][0]);
                acc[inp][n][1] = ffma2(xv.x, w1.x, acc[inp][n][1]);
                acc[inp][n][1] = ffma2(xv.y, w1.y, acc[inp][n][1]);
            }
    }

    // scores via butterfly, H pairs -> smem hbuf (overlays x, now dead)
    float s1[2][5], s2[2][5];
    {
        float a110 = sm[A11_OFF+lane], a111 = sm[A11_OFF+32+lane];
        float a210 = sm[A21_OFF+lane], a211 = sm[A21_OFF+32+lane];
        __syncwarp();   // all lanes' x reads done before hbuf overwrite
        #pragma unroll
        for (int inp = 0; inp < 2; inp++)
            #pragma unroll
            for (int n = 0; n < 5; n++){
                float H0 = hsum(acc[inp][n][0]);
                float H1 = hsum(acc[inp][n][1]);
                s1[inp][n] = wsum(H0*a110 + H1*a111);
                s2[inp][n] = wsum(H0*a210 + H1*a211);
                *(float2*)(ws + inp*320 + n*64 + 2*lane) = make_float2(H0, H1);
            }
    }

    // ---------------- layer 1 softmax over i (column-normalized) -----------------
    float* abuf = ws + 1280;    // attn[inp*32 + i*5 + j]
    {
        int g = lane / 5, j = lane - g*5;
        if (lane < 10){
            float t1[5], t2[5];
            #pragma unroll
            for (int i = 0; i < 5; i++){
                t1[i] = g ? s1[1][i] : s1[0][i];
                t2[i] = g ? s2[1][i] : s2[0][i];
            }
            float t2j = (j==0)?t2[0]:(j==1)?t2[1]:(j==2)?t2[2]:(j==3)?t2[3]:t2[4];
            float ex[5], cs = 0.f;
            #pragma unroll
            for (int i = 0; i < 5; i++){
                float e = t1[i] + t2j;
                e = (e > 0.f) ? e : ALPHA*e;
                ex[i] = __expf(e);
                cs += ex[i];
            }
            float rc = __fdividef(1.f, cs);
            #pragma unroll
            for (int i = 0; i < 5; i++) abuf[g*32 + i*5 + j] = ex[i]*rc;
        }
    }
    __syncwarp();

    // ---------------- layer 1 apply + BN1 + ReLU -> h2s (overlays x[1]) ----------
    float* h2s = ws + 640;      // [inp][n][64]
    {
        float O[2][5][2];
        #pragma unroll
        for (int inp = 0; inp < 2; inp++)
            #pragma unroll
            for (int i = 0; i < 5; i++){ O[inp][i][0] = 0.f; O[inp][i][1] = 0.f; }
        #pragma unroll
        for (int inp = 0; inp < 2; inp++)
            #pragma unroll
            for (int j = 0; j < 5; j++){
                float2 Hp = *(const float2*)(ws + inp*320 + j*64 + 2*lane);
                #pragma unroll
                for (int i = 0; i < 5; i++){
                    float a = abuf[inp*32 + i*5 + j];
                    O[inp][i][0] += a * Hp.x;
                    O[inp][i][1] += a * Hp.y;
                }
            }
        #pragma unroll
        for (int inp = 0; inp < 2; inp++)
            #pragma unroll
            for (int n = 0; n < 5; n++){
                float sc = sm[SC1_OFF+n], sh = sm[SH1_OFF+n];
                h2s[inp*320 + n*64 + lane]      = fmaxf(0.f, O[inp][n][0]*sc + sh);
                h2s[inp*320 + n*64 + 32 + lane] = fmaxf(0.f, O[inp][n][1]*sc + sh);
            }
    }
    __syncwarp();

    // ---------------- layer 2 GEMM: hh[inp][n] at p = lane ----------------
    u64 acc2[2][5];
    #pragma unroll
    for (int inp = 0; inp < 2; inp++)
        #pragma unroll
        for (int n = 0; n < 5; n++) acc2[inp][n] = 0ull;
    const ulonglong2* w2p = (const ulonglong2*)(sm + WT2_OFF);
    #pragma unroll 4
    for (int q = 0; q < 16; ++q){
        ulonglong2 w = w2p[q*32 + lane];
        #pragma unroll
        for (int inp = 0; inp < 2; ++inp)
            #pragma unroll
            for (int n = 0; n < 5; ++n){
                ulonglong2 xv = *(const ulonglong2*)(h2s + inp*320 + n*64 + 4*q);
                acc2[inp][n] = ffma2(xv.x, w.x, acc2[inp][n]);
                acc2[inp][n] = ffma2(xv.y, w.y, acc2[inp][n]);
            }
    }
    float hh[2][5];
    #pragma unroll
    for (int inp = 0; inp < 2; inp++)
        #pragma unroll
        for (int n = 0; n < 5; n++) hh[inp][n] = hsum(acc2[inp][n]);

    // ---------------- layer 2 scores (butterfly) ----------------
    float uu[2][5], wv[2][5];
    {
        float a12l = sm[A12_OFF+lane], a22l = sm[A22_OFF+lane];
        #pragma unroll
        for (int inp = 0; inp < 2; inp++)
            #pragma unroll
            for (int n = 0; n < 5; n++){
                uu[inp][n] = wsum(hh[inp][n]*a12l);
                wv[inp][n] = wsum(hh[inp][n]*a22l);
            }
    }

    // ---------------- layer 2 softmax: g=0 -> ya, g=1 -> yn ----------------
    __syncwarp();   // abuf WAR: layer-1 apply reads done
    {
        int g = lane / 5, j = lane - g*5;
        if (lane < 10){
            float t1[5], t2[5];
            #pragma unroll
            for (int i = 0; i < 5; i++){
                t1[i] = g ? uu[1][i] : uu[0][i];
                t2[i] = g ? wv[0][i] : wv[1][i];
            }
            float t2j = (j==0)?t2[0]:(j==1)?t2[1]:(j==2)?t2[2]:(j==3)?t2[3]:t2[4];
            float ex[5], cs = 0.f;
            #pragma unroll
            for (int i = 0; i < 5; i++){
                float e = t1[i] + t2j;
                e = (e > 0.f) ? e : ALPHA*e;
                ex[i] = __expf(e);
                cs += ex[i];
            }
            float rc = __fdividef(1.f, cs);
            #pragma unroll
            for (int i = 0; i < 5; i++) abuf[g*32 + i*5 + j] = ex[i]*rc;
        }
    }
    __syncwarp();

    // ---------------- layer 2 apply + BN2 + ReLU ----------------
    float y2[2][5];
    #pragma unroll
    for (int g = 0; g < 2; g++)
        #pragma unroll
        for (int i = 0; i < 5; i++){
            float o2 = 0.f;
            #pragma unroll
            for (int j = 0; j < 5; j++)
                o2 += abuf[g*32 + i*5 + j] * hh[g][j];
            y2[g][i] = fmaxf(0.f, o2*sm[SC2_OFF+i] + sm[SH2_OFF+i]);
        }

    // ---------------- final linear (13 outputs), coalesced store ----------------
    u64 f2[5];
    #pragma unroll
    for (int n = 0; n < 5; n++) f2[n] = pk(y2[0][n], y2[1][n]);
    const u64* wlp = (const u64*)(sm + WL2_OFF);
    float res = 0.f;
    #pragma unroll
    for (int k = 0; k < 13; k++){
        u64 a = 0ull;
        #pragma unroll
        for (int n = 0; n < 5; n++)
            a = ffma2(f2[n], wlp[k*160 + n*32 + lane], a);
        float rk = wsum(hsum(a));
        if (lane == k) res = rk + sm[BL_OFF+k];
    }
    if (lane < 13) out[(size_t)b*13 + lane] = res;
}

extern "C" void kernel_launch(void* const* d_in, const int* in_sizes, int n_in,
                              void* d_out, int out_size)
{
    const float* x   = (const float*)d_in[0];
    const float* Wt1 = (const float*)d_in[1];
    const float* a11 = (const float*)d_in[2];
    const float* a21 = (const float*)d_in[3];
    const float* g1  = (const float*)d_in[4];
    const float* b1  = (const float*)d_in[5];
    const float* m1  = (const float*)d_in[6];
    const float* v1  = (const float*)d_in[7];
    const float* Wt2 = (const float*)d_in[8];
    const float* a12 = (const float*)d_in[9];
    const float* a22 = (const float*)d_in[10];
    const float* g2  = (const float*)d_in[11];
    const float* b2  = (const float*)d_in[12];
    const float* m2  = (const float*)d_in[13];
    const float* v2  = (const float*)d_in[14];
    const float* Wl  = (const float*)d_in[15];
    const float* bl  = (const float*)d_in[16];

    int B = in_sizes[0] / 1250;
    size_t smem_bytes = (size_t)SMEM_FLOATS * sizeof(float);
    cudaFuncSetAttribute(gat_fused_kernel,
                         cudaFuncAttributeMaxDynamicSharedMemorySize, (int)smem_bytes);

    dim3 grid((B + WARPS - 1) / WARPS);
    gat_fused_kernel<<<grid, THREADS, smem_bytes>>>(
        x, Wt1, a11, a21, g1, b1, m1, v1,
        Wt2, a12, a22, g2, b2, m2, v2, Wl, bl,
        (float*)d_out, B);
}

// round 4
// speedup vs baseline: 1.8619x; 1.4139x over previous
#include <cuda_runtime.h>

#define ALPHA 0.2f
#define BN_EPS 1e-5f
#define THREADS 512
#define WARPS 16

typedef unsigned int u32;
typedef unsigned long long u64;

__device__ __forceinline__ u32 f2tf(float f){
    u32 r; asm("cvt.rna.tf32.f32 %0, %1;" : "=r"(r) : "f"(f)); return r;
}
__device__ __forceinline__ u64 ffma2(u64 a, u64 b, u64 c){
    u64 d; asm("fma.rn.f32x2 %0, %1, %2, %3;" : "=l"(d) : "l"(a), "l"(b), "l"(c)); return d;
}
__device__ __forceinline__ u64 pk(float lo, float hi){
    u64 r; asm("mov.b64 %0, {%1, %2};" : "=l"(r) : "f"(lo), "f"(hi)); return r;
}
__device__ __forceinline__ float hsum(u64 v){
    float x, y; asm("mov.b64 {%0, %1}, %2;" : "=f"(x), "=f"(y) : "l"(v)); return x + y;
}
__device__ __forceinline__ float wsum(float v){
    #pragma unroll
    for (int d = 16; d > 0; d >>= 1) v += __shfl_xor_sync(0xffffffffu, v, d);
    return v;
}
__device__ __forceinline__ void mma8(float4& d, u32 a0, u32 a1, u32 a2, u32 a3, u32 b0, u32 b1){
    asm("mma.sync.aligned.m16n8k8.row.col.f32.tf32.tf32.f32 "
        "{%0,%1,%2,%3}, {%4,%5,%6,%7}, {%8,%9}, {%0,%1,%2,%3};"
        : "+f"(d.x), "+f"(d.y), "+f"(d.z), "+f"(d.w)
        : "r"(a0), "r"(a1), "r"(a2), "r"(a3), "r"(b0), "r"(b1));
}

// ---- shared memory layout (float offsets) ----
#define BF1_OFF   0        // [16 q][8 t][32 lane] x uint2 (tf32 B frags, layer1) = 8192
#define BF2_OFF   8192     // [8 q][4 t][32] x uint2 = 2048 -> 10240
#define WL2_OFF   10240    // [13 k][5 n][32 lane] float2 = 4160 -> 14400
#define A1F_OFF   14400    // [8 t][4 c] float4 (a11 pair, a21 pair) = 128 -> 14528
#define A2F_OFF   14528    // [4 t][4 c] float4 = 64 -> 14592
#define SC1_OFF   14592
#define SH1_OFF   14600
#define SC2_OFF   14608
#define SH2_OFF   14616
#define BL_OFF    14624    // 13 (pad 16) -> 14640
#define SCR_OFF   14640
#define WSCR      2112     // per-warp scratch
#define SMEM_FLOATS (SCR_OFF + WARPS*WSCR)   // 48432 floats = 193728 bytes

// per-warp scratch offsets (floats)
#define XS_OFF    0        // x tf32 rows: 10 rows stride 132 (A-frag reads span 16*132=2112)
#define H2B_OFF   0        // h2 tf32 rows: 10 rows stride 68 (reads span 1088) — overlays dead xs
#define HB_OFF    1320     // H rows: 10 x stride 66 (later reused stride 34 for hh)
#define SB1_OFF   1984     // layer1 scores float2[10]
#define SB2_OFF   2004     // layer2 scores float2[10]
#define AB_OFF    2048     // attn 64 floats

__global__ void __launch_bounds__(THREADS, 1) gat_fused_kernel(
    const float* __restrict__ x,
    const float* __restrict__ Wt1, const float* __restrict__ a11, const float* __restrict__ a21,
    const float* __restrict__ g1,  const float* __restrict__ b1,  const float* __restrict__ m1, const float* __restrict__ v1,
    const float* __restrict__ Wt2, const float* __restrict__ a12, const float* __restrict__ a22,
    const float* __restrict__ g2,  const float* __restrict__ b2,  const float* __restrict__ m2, const float* __restrict__ v2,
    const float* __restrict__ Wl,  const float* __restrict__ bl,
    float* __restrict__ out, int B)
{
    extern __shared__ float sm[];
    const int tid = threadIdx.x;

    // ---------------- block init: weights -> tf32 fragment layouts ----------------
    {
        uint2* bf1 = (uint2*)(sm + BF1_OFF);
        for (int i = tid; i < 16*8*32; i += THREADS){
            int l = i & 31, t = (i >> 5) & 7, q = i >> 8;
            int n = 8*t + (l >> 2);
            int k = 8*q + (l & 3);
            u32 b0 = (k   < 125) ? f2tf(Wt1[n*125 + k    ]) : 0u;
            u32 b1v= (k+4 < 125) ? f2tf(Wt1[n*125 + k + 4]) : 0u;
            bf1[i] = make_uint2(b0, b1v);
        }
        uint2* bf2 = (uint2*)(sm + BF2_OFF);
        for (int i = tid; i < 8*4*32; i += THREADS){
            int l = i & 31, t = (i >> 5) & 3, q = i >> 7;
            int n = 8*t + (l >> 2);
            int k = 8*q + (l & 3);
            bf2[i] = make_uint2(f2tf(Wt2[n*64 + k]), f2tf(Wt2[n*64 + k + 4]));
        }
        float2* wlp = (float2*)(sm + WL2_OFF);       // [k][n][lane]
        for (int i = tid; i < 13*5*32; i += THREADS){
            int k = i / 160, r = i - k*160;
            int n = r >> 5, l = r & 31;
            wlp[i] = make_float2(Wl[k*320 + n*64 + l], Wl[k*320 + n*64 + 32 + l]);
        }
        float4* a1f = (float4*)(sm + A1F_OFF);
        if (tid < 32){
            int t = tid >> 2, c = tid & 3, n0 = 8*t + 2*c;
            a1f[tid] = make_float4(a11[n0], a11[n0+1], a21[n0], a21[n0+1]);
        }
        float4* a2f = (float4*)(sm + A2F_OFF);
        if (tid >= 32 && tid < 48){
            int j = tid - 32;
            int t = j >> 2, c = j & 3, n0 = 8*t + 2*c;
            a2f[j] = make_float4(a12[n0], a12[n0+1], a22[n0], a22[n0+1]);
        }
        if (tid < 5){
            float sc = g1[tid] * rsqrtf(v1[tid] + BN_EPS);
            sm[SC1_OFF+tid] = sc; sm[SH1_OFF+tid] = b1[tid] - m1[tid]*sc;
            float s2c = g2[tid] * rsqrtf(v2[tid] + BN_EPS);
            sm[SC2_OFF+tid] = s2c; sm[SH2_OFF+tid] = b2[tid] - m2[tid]*s2c;
        }
        if (tid < 13) sm[BL_OFF+tid] = bl[tid];
    }
    __syncthreads();

    const int wid  = tid >> 5, lane = tid & 31;
    const int gid  = lane >> 2, tig = lane & 3;   // fragment coords
    const int b = blockIdx.x * WARPS + wid;
    if (b >= B) return;

    float* ws = sm + SCR_OFF + wid*WSCR;
    u32*   xs = (u32*)(ws + XS_OFF);              // stride 132

    // ---------------- load x -> tf32 A rows: row m = inp*5 + n ----------------
    const float* xg = x + (size_t)b * 1250;
    #pragma unroll
    for (int inp = 0; inp < 2; inp++)
        #pragma unroll
        for (int n = 0; n < 5; n++){
            const float* src = xg + n*250 + inp*125;
            u32* dst = xs + (inp*5 + n)*132;
            dst[lane]      = f2tf(src[lane]);
            dst[lane+32]   = f2tf(src[lane+32]);
            dst[lane+64]   = f2tf(src[lane+64]);
            dst[lane+96]   = (lane+96 < 125) ? f2tf(src[lane+96]) : 0u;
        }
    __syncwarp();

    // ---------------- layer 1 MMA: D[16 x 64] over K=128 ----------------
    float4 d1[8];
    #pragma unroll
    for (int t = 0; t < 8; t++) d1[t] = make_float4(0.f, 0.f, 0.f, 0.f);
    {
        const u32* xa = xs + gid*132 + tig;
        const uint2* bf1 = (const uint2*)(sm + BF1_OFF);
        #pragma unroll
        for (int q = 0; q < 16; q++){
            u32 a0 = xa[8*q];
            u32 a1 = xa[8*132 + 8*q];
            u32 a2 = xa[8*q + 4];
            u32 a3 = xa[8*132 + 8*q + 4];
            #pragma unroll
            for (int t = 0; t < 8; t++){
                uint2 bb = bf1[(q*8 + t)*32 + lane];
                mma8(d1[t], a0, a1, a2, a3, bb.x, bb.y);
            }
        }
    }

    // ---------------- layer 1 scores + spill H rows ----------------
    {
        float s1lo = 0.f, s2lo = 0.f, s1hi = 0.f, s2hi = 0.f;
        const float4* a1f = (const float4*)(sm + A1F_OFF);
        #pragma unroll
        for (int t = 0; t < 8; t++){
            float4 av = a1f[t*4 + tig];
            s1lo += d1[t].x*av.x + d1[t].y*av.y;
            s2lo += d1[t].x*av.z + d1[t].y*av.w;
            s1hi += d1[t].z*av.x + d1[t].w*av.y;
            s2hi += d1[t].z*av.z + d1[t].w*av.w;
        }
        s1lo += __shfl_xor_sync(0xffffffffu, s1lo, 1); s1lo += __shfl_xor_sync(0xffffffffu, s1lo, 2);
        s2lo += __shfl_xor_sync(0xffffffffu, s2lo, 1); s2lo += __shfl_xor_sync(0xffffffffu, s2lo, 2);
        s1hi += __shfl_xor_sync(0xffffffffu, s1hi, 1); s1hi += __shfl_xor_sync(0xffffffffu, s1hi, 2);
        s2hi += __shfl_xor_sync(0xffffffffu, s2hi, 1); s2hi += __shfl_xor_sync(0xffffffffu, s2hi, 2);

        float2* sb = (float2*)(ws + SB1_OFF);
        if (tig == 0){
            sb[gid] = make_float2(s1lo, s2lo);
            if (gid < 2) sb[8 + gid] = make_float2(s1hi, s2hi);
        }
        float* hb = ws + HB_OFF;   // stride 66
        #pragma unroll
        for (int t = 0; t < 8; t++){
            int col = 8*t + 2*tig;
            *(float2*)(hb + gid*66 + col) = make_float2(d1[t].x, d1[t].y);
            if (gid < 2)
                *(float2*)(hb + (gid+8)*66 + col) = make_float2(d1[t].z, d1[t].w);
        }
    }
    __syncwarp();

    // ---------------- layer 1 softmax (column-normalized over i) ----------------
    {
        const float2* sb = (const float2*)(ws + SB1_OFF);
        float* abuf = ws + AB_OFF;
        int g = lane / 5, j = lane - g*5;
        if (lane < 10){
            float t2j = sb[g*5 + j].y;
            float ex[5], cs = 0.f;
            #pragma unroll
            for (int i = 0; i < 5; i++){
                float e = sb[g*5 + i].x + t2j;
                e = (e > 0.f) ? e : ALPHA*e;
                ex[i] = __expf(e);
                cs += ex[i];
            }
            float rc = __fdividef(1.f, cs);
            #pragma unroll
            for (int i = 0; i < 5; i++) abuf[g*32 + i*5 + j] = ex[i]*rc;
        }
    }
    __syncwarp();

    // ---------------- layer 1 apply + BN1 + ReLU -> h2 tf32 rows ----------------
    {
        const float* hb = ws + HB_OFF;
        const float* abuf = ws + AB_OFF;
        float Ox[2][5], Oy[2][5];
        #pragma unroll
        for (int inp = 0; inp < 2; inp++)
            #pragma unroll
            for (int i = 0; i < 5; i++){ Ox[inp][i] = 0.f; Oy[inp][i] = 0.f; }
        #pragma unroll
        for (int inp = 0; inp < 2; inp++)
            #pragma unroll
            for (int j = 0; j < 5; j++){
                float2 Hp = *(const float2*)(hb + (inp*5 + j)*66 + 2*lane);
                #pragma unroll
                for (int i = 0; i < 5; i++){
                    float a = abuf[inp*32 + i*5 + j];
                    Ox[inp][i] += a * Hp.x;
                    Oy[inp][i] += a * Hp.y;
                }
            }
        u32* h2 = (u32*)(ws + H2B_OFF);   // stride 68, xs is dead now
        #pragma unroll
        for (int inp = 0; inp < 2; inp++)
            #pragma unroll
            for (int n = 0; n < 5; n++){
                float sc = sm[SC1_OFF+n], sh = sm[SH1_OFF+n];
                float v0 = fmaxf(0.f, Ox[inp][n]*sc + sh);
                float v1 = fmaxf(0.f, Oy[inp][n]*sc + sh);
                *(uint2*)(h2 + (inp*5 + n)*68 + 2*lane) = make_uint2(f2tf(v0), f2tf(v1));
            }
    }
    __syncwarp();

    // ---------------- layer 2 MMA: D[16 x 32] over K=64 ----------------
    float4 d2[4];
    #pragma unroll
    for (int t = 0; t < 4; t++) d2[t] = make_float4(0.f, 0.f, 0.f, 0.f);
    {
        const u32* ha = (const u32*)(ws + H2B_OFF) + gid*68 + tig;
        const uint2* bf2 = (const uint2*)(sm + BF2_OFF);
        #pragma unroll
        for (int q = 0; q < 8; q++){
            u32 a0 = ha[8*q];
            u32 a1 = ha[8*68 + 8*q];
            u32 a2 = ha[8*q + 4];
            u32 a3 = ha[8*68 + 8*q + 4];
            #pragma unroll
            for (int t = 0; t < 4; t++){
                uint2 bb = bf2[(q*4 + t)*32 + lane];
                mma8(d2[t], a0, a1, a2, a3, bb.x, bb.y);
            }
        }
    }

    // ---------------- layer 2 scores + spill hh rows ----------------
    {
        float ulo = 0.f, wlo = 0.f, uhi = 0.f, whi = 0.f;
        const float4* a2f = (const float4*)(sm + A2F_OFF);
        #pragma unroll
        for (int t = 0; t < 4; t++){
            float4 av = a2f[t*4 + tig];
            ulo += d2[t].x*av.x + d2[t].y*av.y;
            wlo += d2[t].x*av.z + d2[t].y*av.w;
            uhi += d2[t].z*av.x + d2[t].w*av.y;
            whi += d2[t].z*av.z + d2[t].w*av.w;
        }
        ulo += __shfl_xor_sync(0xffffffffu, ulo, 1); ulo += __shfl_xor_sync(0xffffffffu, ulo, 2);
        wlo += __shfl_xor_sync(0xffffffffu, wlo, 1); wlo += __shfl_xor_sync(0xffffffffu, wlo, 2);
        uhi += __shfl_xor_sync(0xffffffffu, uhi, 1); uhi += __shfl_xor_sync(0xffffffffu, uhi, 2);
        whi += __shfl_xor_sync(0xffffffffu, whi, 1); whi += __shfl_xor_sync(0xffffffffu, whi, 2);

        float2* sb2 = (float2*)(ws + SB2_OFF);
        if (tig == 0){
            sb2[gid] = make_float2(ulo, wlo);
            if (gid < 2) sb2[8 + gid] = make_float2(uhi, whi);
        }
        float* hhb = ws + HB_OFF;   // stride 34 (H data dead)
        #pragma unroll
        for (int t = 0; t < 4; t++){
            int col = 8*t + 2*tig;
            *(float2*)(hhb + gid*34 + col) = make_float2(d2[t].x, d2[t].y);
            if (gid < 2)
                *(float2*)(hhb + (gid+8)*34 + col) = make_float2(d2[t].z, d2[t].w);
        }
    }
    __syncwarp();

    // ---------------- layer 2 softmax: g=0 -> ya (s2 from xn), g=1 -> yn ----------
    {
        const float2* sb2 = (const float2*)(ws + SB2_OFF);
        float* abuf = ws + AB_OFF;
        int g = lane / 5, j = lane - g*5;
        if (lane < 10){
            float t2j = sb2[(1-g)*5 + j].y;
            float ex[5], cs = 0.f;
            #pragma unroll
            for (int i = 0; i < 5; i++){
                float e = sb2[g*5 + i].x + t2j;
                e = (e > 0.f) ? e : ALPHA*e;
                ex[i] = __expf(e);
                cs += ex[i];
            }
            float rc = __fdividef(1.f, cs);
            #pragma unroll
            for (int i = 0; i < 5; i++) abuf[g*32 + i*5 + j] = ex[i]*rc;
        }
    }
    __syncwarp();

    // ---------------- layer 2 apply + BN2 + ReLU ----------------
    float y2[2][5];
    {
        const float* hhb = ws + HB_OFF;
        const float* abuf = ws + AB_OFF;
        float hv[2][5];
        #pragma unroll
        for (int g = 0; g < 2; g++)
            #pragma unroll
            for (int j = 0; j < 5; j++)
                hv[g][j] = hhb[(g*5 + j)*34 + lane];
        #pragma unroll
        for (int g = 0; g < 2; g++)
            #pragma unroll
            for (int i = 0; i < 5; i++){
                float o2 = 0.f;
                #pragma unroll
                for (int j = 0; j < 5; j++)
                    o2 += abuf[g*32 + i*5 + j] * hv[g][j];
                y2[g][i] = fmaxf(0.f, o2*sm[SC2_OFF+i] + sm[SH2_OFF+i]);
            }
    }

    // ---------------- final linear (13 outputs), coalesced store ----------------
    u64 f2_[5];
    #pragma unroll
    for (int n = 0; n < 5; n++) f2_[n] = pk(y2[0][n], y2[1][n]);
    const u64* wlp = (const u64*)(sm + WL2_OFF);
    float res = 0.f;
    #pragma unroll
    for (int k = 0; k < 13; k++){
        u64 a = 0ull;
        #pragma unroll
        for (int n = 0; n < 5; n++)
            a = ffma2(f2_[n], wlp[k*160 + n*32 + lane], a);
        float rk = wsum(hsum(a));
        if (lane == k) res = rk + sm[BL_OFF+k];
    }
    if (lane < 13) out[(size_t)b*13 + lane] = res;
}

extern "C" void kernel_launch(void* const* d_in, const int* in_sizes, int n_in,
                              void* d_out, int out_size)
{
    const float* x   = (const float*)d_in[0];
    const float* Wt1 = (const float*)d_in[1];
    const float* a11 = (const float*)d_in[2];
    const float* a21 = (const float*)d_in[3];
    const float* g1  = (const float*)d_in[4];
    const float* b1  = (const float*)d_in[5];
    const float* m1  = (const float*)d_in[6];
    const float* v1  = (const float*)d_in[7];
    const float* Wt2 = (const float*)d_in[8];
    const float* a12 = (const float*)d_in[9];
    const float* a22 = (const float*)d_in[10];
    const float* g2  = (const float*)d_in[11];
    const float* b2  = (const float*)d_in[12];
    const float* m2  = (const float*)d_in[13];
    const float* v2  = (const float*)d_in[14];
    const float* Wl  = (const float*)d_in[15];
    const float* bl  = (const float*)d_in[16];

    int B = in_sizes[0] / 1250;
    size_t smem_bytes = (size_t)SMEM_FLOATS * sizeof(float);
    cudaFuncSetAttribute(gat_fused_kernel,
                         cudaFuncAttributeMaxDynamicSharedMemorySize, (int)smem_bytes);

    dim3 grid((B + WARPS - 1) / WARPS);
    gat_fused_kernel<<<grid, THREADS, smem_bytes>>>(
        x, Wt1, a11, a21, g1, b1, m1, v1,
        Wt2, a12, a22, g2, b2, m2, v2, Wl, bl,
        (float*)d_out, B);
}

// round 6
// speedup vs baseline: 2.2312x; 1.1983x over previous
#include <cuda_runtime.h>

#define ALPHA 0.2f
#define BN_EPS 1e-5f
#define THREADS 512
#define WARPS 16

typedef unsigned int u32;
typedef unsigned long long u64;

__device__ __forceinline__ u32 f2tf(float f){
    u32 r; asm("cvt.rna.tf32.f32 %0, %1;" : "=r"(r) : "f"(f)); return r;
}
__device__ __forceinline__ u64 ffma2(u64 a, u64 b, u64 c){
    u64 d; asm("fma.rn.f32x2 %0, %1, %2, %3;" : "=l"(d) : "l"(a), "l"(b), "l"(c)); return d;
}
__device__ __forceinline__ u64 pk(float lo, float hi){
    u64 r; asm("mov.b64 %0, {%1, %2};" : "=l"(r) : "f"(lo), "f"(hi)); return r;
}
__device__ __forceinline__ float hsum(u64 v){
    float x, y; asm("mov.b64 {%0, %1}, %2;" : "=f"(x), "=f"(y) : "l"(v)); return x + y;
}
__device__ __forceinline__ float wsum(float v){
    #pragma unroll
    for (int d = 16; d > 0; d >>= 1) v += __shfl_xor_sync(0xffffffffu, v, d);
    return v;
}
__device__ __forceinline__ void mma8(float4& d, u32 a0, u32 a1, u32 a2, u32 a3, u32 b0, u32 b1){
    asm("mma.sync.aligned.m16n8k8.row.col.f32.tf32.tf32.f32 "
        "{%0,%1,%2,%3}, {%4,%5,%6,%7}, {%8,%9}, {%0,%1,%2,%3};"
        : "+f"(d.x), "+f"(d.y), "+f"(d.z), "+f"(d.w)
        : "r"(a0), "r"(a1), "r"(a2), "r"(a3), "r"(b0), "r"(b1));
}

// ---- shared memory layout (float offsets) ----
#define BF1_OFF   0        // [16 q][8 t][32 lane] uint2 tf32 B frags layer1 = 8192
#define BF2_OFF   8192     // [8 q][4 t][32] uint2 = 2048 -> 10240
#define WL2_OFF   10240    // [13 k][5 n][32 lane] float2 = 4160 -> 14400
#define A1F_OFF   14400    // [8 t][4 c] float4 -> 14528
#define A2F_OFF   14528    // [4 t][4 c] float4 -> 14592
#define SC1_OFF   14592
#define SH1_OFF   14600
#define SC2_OFF   14608
#define SH2_OFF   14616
#define BL_OFF    14624    // 13 (pad 16) -> 14640
#define SCR_OFF   14640
// per-warp scratch (2640 floats):
//   phase 1: xs0 [0,1320), xs1 [1320,2640)  (tf32 x rows, stride 132; phantom
//            hi-rows (m>=10) are redirected to row 0 — never out of bounds)
//   phase 2 overlays:
//     R0 [0,680): HB0 -> h2_0 -> hh_0      R1 [680,1360): HB1 -> h2_1 -> hh_1
//     SB1 [1360,1400): scores L1 (2 x float2[10])
//     SB2 [1400,1440): scores L2
//     AB  [1440,1504): attn buffer (sequential per batch)
#define WSCR      2640
#define SMEM_FLOATS (SCR_OFF + WARPS*WSCR)   // 56880 floats = 227520 bytes

__global__ void __launch_bounds__(THREADS, 1) gat_fused_kernel(
    const float* __restrict__ x,
    const float* __restrict__ Wt1, const float* __restrict__ a11, const float* __restrict__ a21,
    const float* __restrict__ g1,  const float* __restrict__ b1,  const float* __restrict__ m1, const float* __restrict__ v1,
    const float* __restrict__ Wt2, const float* __restrict__ a12, const float* __restrict__ a22,
    const float* __restrict__ g2,  const float* __restrict__ b2,  const float* __restrict__ m2, const float* __restrict__ v2,
    const float* __restrict__ Wl,  const float* __restrict__ bl,
    float* __restrict__ out, int B)
{
    extern __shared__ float sm[];
    const int tid = threadIdx.x;

    // ---------------- block init: weights -> tf32 fragment layouts ----------------
    {
        uint2* bf1 = (uint2*)(sm + BF1_OFF);
        for (int i = tid; i < 16*8*32; i += THREADS){
            int l = i & 31, t = (i >> 5) & 7, q = i >> 8;
            int n = 8*t + (l >> 2);
            int k = 8*q + (l & 3);
            u32 b0 = (k   < 125) ? f2tf(Wt1[n*125 + k    ]) : 0u;
            u32 b1v= (k+4 < 125) ? f2tf(Wt1[n*125 + k + 4]) : 0u;
            bf1[i] = make_uint2(b0, b1v);
        }
        uint2* bf2 = (uint2*)(sm + BF2_OFF);
        for (int i = tid; i < 8*4*32; i += THREADS){
            int l = i & 31, t = (i >> 5) & 3, q = i >> 7;
            int n = 8*t + (l >> 2);
            int k = 8*q + (l & 3);
            bf2[i] = make_uint2(f2tf(Wt2[n*64 + k]), f2tf(Wt2[n*64 + k + 4]));
        }
        float2* wlp = (float2*)(sm + WL2_OFF);       // [k][n][lane]
        for (int i = tid; i < 13*5*32; i += THREADS){
            int k = i / 160, r = i - k*160;
            int n = r >> 5, l = r & 31;
            wlp[i] = make_float2(Wl[k*320 + n*64 + l], Wl[k*320 + n*64 + 32 + l]);
        }
        float4* a1f = (float4*)(sm + A1F_OFF);
        if (tid < 32){
            int t = tid >> 2, c = tid & 3, n0 = 8*t + 2*c;
            a1f[tid] = make_float4(a11[n0], a11[n0+1], a21[n0], a21[n0+1]);
        }
        float4* a2f = (float4*)(sm + A2F_OFF);
        if (tid >= 32 && tid < 48){
            int j = tid - 32;
            int t = j >> 2, c = j & 3, n0 = 8*t + 2*c;
            a2f[j] = make_float4(a12[n0], a12[n0+1], a22[n0], a22[n0+1]);
        }
        if (tid < 5){
            float sc = g1[tid] * rsqrtf(v1[tid] + BN_EPS);
            sm[SC1_OFF+tid] = sc; sm[SH1_OFF+tid] = b1[tid] - m1[tid]*sc;
            float s2c = g2[tid] * rsqrtf(v2[tid] + BN_EPS);
            sm[SC2_OFF+tid] = s2c; sm[SH2_OFF+tid] = b2[tid] - m2[tid]*s2c;
        }
        if (tid < 13) sm[BL_OFF+tid] = bl[tid];
    }
    __syncthreads();

    const int wid  = tid >> 5, lane = tid & 31;
    const int gid  = lane >> 2, tig = lane & 3;   // fragment coords
    const int hi_ok = (gid < 2);
    const int b0i = (blockIdx.x * WARPS + wid) * 2;
    if (b0i >= B) return;

    float* ws = sm + SCR_OFF + wid*WSCR;

    // ---------------- load x (2 batches) -> tf32 A rows, stride 132 ----------------
    #pragma unroll
    for (int bi = 0; bi < 2; bi++){
        const float* xg = x + (size_t)(b0i + bi) * 1250;
        u32* xsb = (u32*)ws + bi*1320;
        #pragma unroll
        for (int inp = 0; inp < 2; inp++)
            #pragma unroll
            for (int n = 0; n < 5; n++){
                const float* src = xg + n*250 + inp*125;
                u32* dst = xsb + (inp*5 + n)*132;
                dst[lane]      = f2tf(src[lane]);
                dst[lane+32]   = f2tf(src[lane+32]);
                dst[lane+64]   = f2tf(src[lane+64]);
                dst[lane+96]   = (lane+96 < 125) ? f2tf(src[lane+96]) : 0u;
            }
    }
    __syncwarp();

    // ---------------- layer 1 MMA (both batches share B-frag loads) ----------------
    // hi rows (gid+8): only gid<2 map to real rows; others redirected to row 0 (safe,
    // results discarded).
    float4 d1[2][8];
    #pragma unroll
    for (int bi = 0; bi < 2; bi++)
        #pragma unroll
        for (int t = 0; t < 8; t++) d1[bi][t] = make_float4(0.f, 0.f, 0.f, 0.f);
    {
        const int hi_row = hi_ok ? (gid+8)*132 : 0;
        const u32* xa0lo = (const u32*)ws + gid*132 + tig;
        const u32* xa0hi = (const u32*)ws + hi_row + tig;
        const u32* xa1lo = xa0lo + 1320;
        const u32* xa1hi = xa0hi + 1320;
        const uint2* bf1 = (const uint2*)(sm + BF1_OFF);
        #pragma unroll
        for (int q = 0; q < 16; q++){
            u32 a00 = xa0lo[8*q],     a01 = xa0hi[8*q];
            u32 a02 = xa0lo[8*q + 4], a03 = xa0hi[8*q + 4];
            u32 a10 = xa1lo[8*q],     a11r= xa1hi[8*q];
            u32 a12r= xa1lo[8*q + 4], a13 = xa1hi[8*q + 4];
            #pragma unroll
            for (int t = 0; t < 8; t++){
                uint2 bb = bf1[(q*8 + t)*32 + lane];
                mma8(d1[0][t], a00, a01, a02, a03, bb.x, bb.y);
                mma8(d1[1][t], a10, a11r, a12r, a13, bb.x, bb.y);
            }
        }
    }
    __syncwarp();   // all xs reads done before overlay writes

    // ---------------- layer 1 scores + spill H rows (stride 68) ----------------
    #pragma unroll
    for (int bi = 0; bi < 2; bi++){
        float s1lo = 0.f, s2lo = 0.f, s1hi = 0.f, s2hi = 0.f;
        const float4* a1f = (const float4*)(sm + A1F_OFF);
        #pragma unroll
        for (int t = 0; t < 8; t++){
            float4 av = a1f[t*4 + tig];
            s1lo += d1[bi][t].x*av.x + d1[bi][t].y*av.y;
            s2lo += d1[bi][t].x*av.z + d1[bi][t].y*av.w;
            s1hi += d1[bi][t].z*av.x + d1[bi][t].w*av.y;
            s2hi += d1[bi][t].z*av.z + d1[bi][t].w*av.w;
        }
        s1lo += __shfl_xor_sync(0xffffffffu, s1lo, 1); s1lo += __shfl_xor_sync(0xffffffffu, s1lo, 2);
        s2lo += __shfl_xor_sync(0xffffffffu, s2lo, 1); s2lo += __shfl_xor_sync(0xffffffffu, s2lo, 2);
        s1hi += __shfl_xor_sync(0xffffffffu, s1hi, 1); s1hi += __shfl_xor_sync(0xffffffffu, s1hi, 2);
        s2hi += __shfl_xor_sync(0xffffffffu, s2hi, 1); s2hi += __shfl_xor_sync(0xffffffffu, s2hi, 2);

        float2* sb = (float2*)(ws + 1360) + bi*10;
        if (tig == 0){
            sb[gid] = make_float2(s1lo, s2lo);
            if (hi_ok) sb[8 + gid] = make_float2(s1hi, s2hi);
        }
        float* hb = ws + bi*680;   // stride 68
        #pragma unroll
        for (int t = 0; t < 8; t++){
            int col = 8*t + 2*tig;
            *(float2*)(hb + gid*68 + col) = make_float2(d1[bi][t].x, d1[bi][t].y);
            if (hi_ok)
                *(float2*)(hb + (gid+8)*68 + col) = make_float2(d1[bi][t].z, d1[bi][t].w);
        }
    }
    __syncwarp();

    // ---------------- per batch: softmax1, apply1 + BN1 + ReLU -> h2 (overlay) ----
    #pragma unroll
    for (int bi = 0; bi < 2; bi++){
        {
            const float2* sb = (const float2*)(ws + 1360) + bi*10;
            float* abuf = ws + 1440;
            int g = lane / 5, j = lane - g*5;
            if (lane < 10){
                float t2j = sb[g*5 + j].y;
                float ex[5], cs = 0.f;
                #pragma unroll
                for (int i = 0; i < 5; i++){
                    float e = sb[g*5 + i].x + t2j;
                    e = (e > 0.f) ? e : ALPHA*e;
                    ex[i] = __expf(e);
                    cs += ex[i];
                }
                float rc = __fdividef(1.f, cs);
                #pragma unroll
                for (int i = 0; i < 5; i++) abuf[g*32 + i*5 + j] = ex[i]*rc;
            }
        }
        __syncwarp();
        {
            const float* hb = ws + bi*680;
            const float* abuf = ws + 1440;
            float Ox[2][5], Oy[2][5];
            #pragma unroll
            for (int inp = 0; inp < 2; inp++)
                #pragma unroll
                for (int i = 0; i < 5; i++){ Ox[inp][i] = 0.f; Oy[inp][i] = 0.f; }
            #pragma unroll
            for (int inp = 0; inp < 2; inp++)
                #pragma unroll
                for (int j = 0; j < 5; j++){
                    float2 Hp = *(const float2*)(hb + (inp*5 + j)*68 + 2*lane);
                    #pragma unroll
                    for (int i = 0; i < 5; i++){
                        float a = abuf[inp*32 + i*5 + j];
                        Ox[inp][i] += a * Hp.x;
                        Oy[inp][i] += a * Hp.y;
                    }
                }
            __syncwarp();   // all HB reads done before h2 overlay
            u32* h2 = (u32*)(ws + bi*680);   // stride 68
            #pragma unroll
            for (int inp = 0; inp < 2; inp++)
                #pragma unroll
                for (int n = 0; n < 5; n++){
                    float sc = sm[SC1_OFF+n], sh = sm[SH1_OFF+n];
                    float v0 = fmaxf(0.f, Ox[inp][n]*sc + sh);
                    float v1 = fmaxf(0.f, Oy[inp][n]*sc + sh);
                    *(uint2*)(h2 + (inp*5 + n)*68 + 2*lane) = make_uint2(f2tf(v0), f2tf(v1));
                }
        }
        __syncwarp();
    }

    // ---------------- layer 2 MMA (shared B-frag loads) ----------------
    float4 d2[2][4];
    #pragma unroll
    for (int bi = 0; bi < 2; bi++)
        #pragma unroll
        for (int t = 0; t < 4; t++) d2[bi][t] = make_float4(0.f, 0.f, 0.f, 0.f);
    {
        const int hi_row2 = hi_ok ? (gid+8)*68 : 0;
        const u32* ha0lo = (const u32*)ws + gid*68 + tig;
        const u32* ha0hi = (const u32*)ws + hi_row2 + tig;
        const u32* ha1lo = ha0lo + 680;
        const u32* ha1hi = ha0hi + 680;
        const uint2* bf2 = (const uint2*)(sm + BF2_OFF);
        #pragma unroll
        for (int q = 0; q < 8; q++){
            u32 a00 = ha0lo[8*q],     a01 = ha0hi[8*q];
            u32 a02 = ha0lo[8*q + 4], a03 = ha0hi[8*q + 4];
            u32 a10 = ha1lo[8*q],     a11r= ha1hi[8*q];
            u32 a12r= ha1lo[8*q + 4], a13 = ha1hi[8*q + 4];
            #pragma unroll
            for (int t = 0; t < 4; t++){
                uint2 bb = bf2[(q*4 + t)*32 + lane];
                mma8(d2[0][t], a00, a01, a02, a03, bb.x, bb.y);
                mma8(d2[1][t], a10, a11r, a12r, a13, bb.x, bb.y);
            }
        }
    }
    __syncwarp();   // h2 reads done before hh overlay

    // ---------------- layer 2 scores + spill hh rows (stride 34) ----------------
    #pragma unroll
    for (int bi = 0; bi < 2; bi++){
        float ulo = 0.f, wlo = 0.f, uhi = 0.f, whi = 0.f;
        const float4* a2f = (const float4*)(sm + A2F_OFF);
        #pragma unroll
        for (int t = 0; t < 4; t++){
            float4 av = a2f[t*4 + tig];
            ulo += d2[bi][t].x*av.x + d2[bi][t].y*av.y;
            wlo += d2[bi][t].x*av.z + d2[bi][t].y*av.w;
            uhi += d2[bi][t].z*av.x + d2[bi][t].w*av.y;
            whi += d2[bi][t].z*av.z + d2[bi][t].w*av.w;
        }
        ulo += __shfl_xor_sync(0xffffffffu, ulo, 1); ulo += __shfl_xor_sync(0xffffffffu, ulo, 2);
        wlo += __shfl_xor_sync(0xffffffffu, wlo, 1); wlo += __shfl_xor_sync(0xffffffffu, wlo, 2);
        uhi += __shfl_xor_sync(0xffffffffu, uhi, 1); uhi += __shfl_xor_sync(0xffffffffu, uhi, 2);
        whi += __shfl_xor_sync(0xffffffffu, whi, 1); whi += __shfl_xor_sync(0xffffffffu, whi, 2);

        float2* sb2 = (float2*)(ws + 1400) + bi*10;
        if (tig == 0){
            sb2[gid] = make_float2(ulo, wlo);
            if (hi_ok) sb2[8 + gid] = make_float2(uhi, whi);
        }
        float* hhb = ws + bi*680;   // stride 34
        #pragma unroll
        for (int t = 0; t < 4; t++){
            int col = 8*t + 2*tig;
            *(float2*)(hhb + gid*34 + col) = make_float2(d2[bi][t].x, d2[bi][t].y);
            if (hi_ok)
                *(float2*)(hhb + (gid+8)*34 + col) = make_float2(d2[bi][t].z, d2[bi][t].w);
        }
    }
    __syncwarp();

    // ---------------- per batch: softmax2, apply2 + BN2 + ReLU -> y2 ----------------
    float y2[2][2][5];
    #pragma unroll
    for (int bi = 0; bi < 2; bi++){
        {
            const float2* sb2 = (const float2*)(ws + 1400) + bi*10;
            float* abuf = ws + 1440;
            int g = lane / 5, j = lane - g*5;
            if (lane < 10){
                float t2j = sb2[(1-g)*5 + j].y;
                float ex[5], cs = 0.f;
                #pragma unroll
                for (int i = 0; i < 5; i++){
                    float e = sb2[g*5 + i].x + t2j;
                    e = (e > 0.f) ? e : ALPHA*e;
                    ex[i] = __expf(e);
                    cs += ex[i];
                }
                float rc = __fdividef(1.f, cs);
                #pragma unroll
                for (int i = 0; i < 5; i++) abuf[g*32 + i*5 + j] = ex[i]*rc;
            }
        }
        __syncwarp();
        {
            const float* hhb = ws + bi*680;
            const float* abuf = ws + 1440;
            float hv[2][5];
            #pragma unroll
            for (int g = 0; g < 2; g++)
                #pragma unroll
                for (int j = 0; j < 5; j++)
                    hv[g][j] = hhb[(g*5 + j)*34 + lane];
            #pragma unroll
            for (int g = 0; g < 2; g++)
                #pragma unroll
                for (int i = 0; i < 5; i++){
                    float o2 = 0.f;
                    #pragma unroll
                    for (int j = 0; j < 5; j++)
                        o2 += abuf[g*32 + i*5 + j] * hv[g][j];
                    y2[bi][g][i] = fmaxf(0.f, o2*sm[SC2_OFF+i] + sm[SH2_OFF+i]);
                }
        }
        __syncwarp();
    }

    // ---------------- final linear (shared Wl loads, both batches) ----------------
    u64 f2a[5], f2b[5];
    #pragma unroll
    for (int n = 0; n < 5; n++){
        f2a[n] = pk(y2[0][0][n], y2[0][1][n]);
        f2b[n] = pk(y2[1][0][n], y2[1][1][n]);
    }
    const u64* wlp = (const u64*)(sm + WL2_OFF);
    float res0 = 0.f, res1 = 0.f;
    #pragma unroll
    for (int k = 0; k < 13; k++){
        u64 aa = 0ull, ab = 0ull;
        #pragma unroll
        for (int n = 0; n < 5; n++){
            u64 w = wlp[k*160 + n*32 + lane];
            aa = ffma2(f2a[n], w, aa);
            ab = ffma2(f2b[n], w, ab);
        }
        float r0 = wsum(hsum(aa));
        float r1 = wsum(hsum(ab));
        if (lane == k){ res0 = r0 + sm[BL_OFF+k]; res1 = r1 + sm[BL_OFF+k]; }
    }
    if (lane < 13){
        out[(size_t)b0i*13 + lane] = res0;
        out[(size_t)(b0i+1)*13 + lane] = res1;
    }
}

extern "C" void kernel_launch(void* const* d_in, const int* in_sizes, int n_in,
                              void* d_out, int out_size)
{
    const float* x   = (const float*)d_in[0];
    const float* Wt1 = (const float*)d_in[1];
    const float* a11 = (const float*)d_in[2];
    const float* a21 = (const float*)d_in[3];
    const float* g1  = (const float*)d_in[4];
    const float* b1  = (const float*)d_in[5];
    const float* m1  = (const float*)d_in[6];
    const float* v1  = (const float*)d_in[7];
    const float* Wt2 = (const float*)d_in[8];
    const float* a12 = (const float*)d_in[9];
    const float* a22 = (const float*)d_in[10];
    const float* g2  = (const float*)d_in[11];
    const float* b2  = (const float*)d_in[12];
    const float* m2  = (const float*)d_in[13];
    const float* v2  = (const float*)d_in[14];
    const float* Wl  = (const float*)d_in[15];
    const float* bl  = (const float*)d_in[16];

    int B = in_sizes[0] / 1250;
    size_t smem_bytes = (size_t)SMEM_FLOATS * sizeof(float);
    cudaFuncSetAttribute(gat_fused_kernel,
                         cudaFuncAttributeMaxDynamicSharedMemorySize, (int)smem_bytes);

    int batches_per_block = WARPS * 2;
    dim3 grid((B + batches_per_block - 1) / batches_per_block);
    gat_fused_kernel<<<grid, THREADS, smem_bytes>>>(
        x, Wt1, a11, a21, g1, b1, m1, v1,
        Wt2, a12, a22, g2, b2, m2, v2, Wl, bl,
        (float*)d_out, B);
}

// round 7
// speedup vs baseline: 2.5056x; 1.1230x over previous
#include <cuda_runtime.h>
#include <cuda_fp16.h>

#define ALPHA 0.2f
#define BN_EPS 1e-5f
#define THREADS 640
#define WARPS 20

typedef unsigned int u32;
typedef unsigned long long u64;

__device__ __forceinline__ u32 pkh(float a, float b){
    __half2 h = __floats2half2_rn(a, b);
    return *(u32*)&h;
}
__device__ __forceinline__ u64 ffma2(u64 a, u64 b, u64 c){
    u64 d; asm("fma.rn.f32x2 %0, %1, %2, %3;" : "=l"(d) : "l"(a), "l"(b), "l"(c)); return d;
}
__device__ __forceinline__ u64 pk(float lo, float hi){
    u64 r; asm("mov.b64 %0, {%1, %2};" : "=l"(r) : "f"(lo), "f"(hi)); return r;
}
__device__ __forceinline__ float hsum(u64 v){
    float x, y; asm("mov.b64 {%0, %1}, %2;" : "=f"(x), "=f"(y) : "l"(v)); return x + y;
}
__device__ __forceinline__ float wsum(float v){
    #pragma unroll
    for (int d = 16; d > 0; d >>= 1) v += __shfl_xor_sync(0xffffffffu, v, d);
    return v;
}
// m16n8k16 fp16 MMA, fp32 accum
__device__ __forceinline__ void mma16(float4& d, u32 a0, u32 a1, u32 a2, u32 a3, u32 b0, u32 b1){
    asm("mma.sync.aligned.m16n8k16.row.col.f32.f16.f16.f32 "
        "{%0,%1,%2,%3}, {%4,%5,%6,%7}, {%8,%9}, {%0,%1,%2,%3};"
        : "+f"(d.x), "+f"(d.y), "+f"(d.z), "+f"(d.w)
        : "r"(a0), "r"(a1), "r"(a2), "r"(a3), "r"(b0), "r"(b1));
}

// ---- shared memory layout (32-bit slots) ----
#define BF1_OFF   0        // [8 q][8 t][32 lane] uint2 fp16 B frags L1 = 4096 slots
#define BF2_OFF   4096     // [4 q][4 t][32] uint2 = 1024 -> 5120
#define WL2_OFF   5120     // [13 k][5 n][32 lane] float2 = 4160 -> 9280
#define A1F_OFF   9280     // [8 t][4 c] float4 -> 9408
#define A2F_OFF   9408     // [4 t][4 c] float4 -> 9472
#define SC1_OFF   9472
#define SH1_OFF   9480
#define SC2_OFF   9488
#define SH2_OFF   9496
#define BL_OFF    9504     // 13 (pad 16) -> 9520
#define SCR_OFF   9520
// per-warp scratch (1568 slots):
//   phase 1: xh[2][10 rows][68 u32] fp16x2 x rows = 1360
//   overlays in [0,1360): H f32 (stride 68, 680/batch) -> h2 fp16x2 (stride 36,
//                         360/batch) -> hh f32 (stride 34, 340/batch)
//   SB1 [1360,1400)  SB2 [1400,1440)  AB [1440,1568): attn 2 x 64
#define WSCR      1568
#define SMEM_FLOATS (SCR_OFF + WARPS*WSCR)   // 40880 slots = 163520 bytes

__global__ void __launch_bounds__(THREADS, 1) gat_fused_kernel(
    const float* __restrict__ x,
    const float* __restrict__ Wt1, const float* __restrict__ a11, const float* __restrict__ a21,
    const float* __restrict__ g1,  const float* __restrict__ b1,  const float* __restrict__ m1, const float* __restrict__ v1,
    const float* __restrict__ Wt2, const float* __restrict__ a12, const float* __restrict__ a22,
    const float* __restrict__ g2,  const float* __restrict__ b2,  const float* __restrict__ m2, const float* __restrict__ v2,
    const float* __restrict__ Wl,  const float* __restrict__ bl,
    float* __restrict__ out, int B)
{
    extern __shared__ float sm[];
    const int tid = threadIdx.x;

    // ---------------- block init: weights -> fp16 fragment layouts ----------------
    {
        uint2* bf1 = (uint2*)(sm + BF1_OFF);
        for (int i = tid; i < 8*8*32; i += THREADS){
            int l = i & 31, t = (i >> 5) & 7, q = i >> 8;
            int n = 8*t + (l >> 2);
            int k0 = 16*q + 2*(l & 3);
            float w0 = (k0   < 125) ? Wt1[n*125 + k0    ] : 0.f;
            float w1 = (k0+1 < 125) ? Wt1[n*125 + k0 + 1] : 0.f;
            float w8 = (k0+8 < 125) ? Wt1[n*125 + k0 + 8] : 0.f;
            float w9 = (k0+9 < 125) ? Wt1[n*125 + k0 + 9] : 0.f;
            bf1[i] = make_uint2(pkh(w0, w1), pkh(w8, w9));
        }
        uint2* bf2 = (uint2*)(sm + BF2_OFF);
        for (int i = tid; i < 4*4*32; i += THREADS){
            int l = i & 31, t = (i >> 5) & 3, q = i >> 7;
            int n = 8*t + (l >> 2);
            int k0 = 16*q + 2*(l & 3);
            bf2[i] = make_uint2(pkh(Wt2[n*64 + k0    ], Wt2[n*64 + k0 + 1]),
                                pkh(Wt2[n*64 + k0 + 8], Wt2[n*64 + k0 + 9]));
        }
        float2* wlp = (float2*)(sm + WL2_OFF);       // [k][n][lane]
        for (int i = tid; i < 13*5*32; i += THREADS){
            int k = i / 160, r = i - k*160;
            int n = r >> 5, l = r & 31;
            wlp[i] = make_float2(Wl[k*320 + n*64 + l], Wl[k*320 + n*64 + 32 + l]);
        }
        float4* a1f = (float4*)(sm + A1F_OFF);
        if (tid < 32){
            int t = tid >> 2, c = tid & 3, n0 = 8*t + 2*c;
            a1f[tid] = make_float4(a11[n0], a11[n0+1], a21[n0], a21[n0+1]);
        }
        float4* a2f = (float4*)(sm + A2F_OFF);
        if (tid >= 32 && tid < 48){
            int j = tid - 32;
            int t = j >> 2, c = j & 3, n0 = 8*t + 2*c;
            a2f[j] = make_float4(a12[n0], a12[n0+1], a22[n0], a22[n0+1]);
        }
        if (tid < 5){
            float sc = g1[tid] * rsqrtf(v1[tid] + BN_EPS);
            sm[SC1_OFF+tid] = sc; sm[SH1_OFF+tid] = b1[tid] - m1[tid]*sc;
            float s2c = g2[tid] * rsqrtf(v2[tid] + BN_EPS);
            sm[SC2_OFF+tid] = s2c; sm[SH2_OFF+tid] = b2[tid] - m2[tid]*s2c;
        }
        if (tid < 13) sm[BL_OFF+tid] = bl[tid];
    }
    __syncthreads();

    const int wid  = tid >> 5, lane = tid & 31;
    const int gid  = lane >> 2, tig = lane & 3;   // fragment coords
    const int hi_ok = (gid < 2);
    const int b0i = (blockIdx.x * WARPS + wid) * 2;
    if (b0i >= B) return;
    const int has_b1 = (b0i + 1 < B);
    const int b1i = has_b1 ? (b0i + 1) : b0i;

    float* ws = sm + SCR_OFF + wid*WSCR;
    u32*   xh = (u32*)ws;                    // fp16x2 x rows, stride 68 u32

    // ---------------- load x (2 batches) -> fp16 A rows ----------------
    {
        const int L2 = 2*lane;
        #pragma unroll
        for (int bi = 0; bi < 2; bi++){
            const float* xg = x + (size_t)(bi ? b1i : b0i) * 1250;
            u32* xsb = xh + bi*680;
            #pragma unroll
            for (int inp = 0; inp < 2; inp++)
                #pragma unroll
                for (int n = 0; n < 5; n++){
                    const float* src = xg + n*250 + inp*125;
                    u32* dst = xsb + (inp*5 + n)*68;
                    dst[lane] = pkh(src[L2], src[L2+1]);
                    float c0 = (L2+64 < 125) ? src[L2+64] : 0.f;
                    float c1 = (L2+65 < 125) ? src[L2+65] : 0.f;
                    dst[lane+32] = pkh(c0, c1);
                }
        }
    }
    __syncwarp();

    // ---------------- layer 1 MMA: K=128 in 8 k16-steps, N=64 in 8 tiles --------
    float4 d1[2][8];
    #pragma unroll
    for (int bi = 0; bi < 2; bi++)
        #pragma unroll
        for (int t = 0; t < 8; t++) d1[bi][t] = make_float4(0.f, 0.f, 0.f, 0.f);
    {
        const int hi_row = hi_ok ? (gid+8)*68 : 0;
        const u32* xa0lo = xh + gid*68 + tig;
        const u32* xa0hi = xh + hi_row + tig;
        const u32* xa1lo = xa0lo + 680;
        const u32* xa1hi = xa0hi + 680;
        const uint2* bf1 = (const uint2*)(sm + BF1_OFF);
        #pragma unroll
        for (int q = 0; q < 8; q++){
            u32 a00 = xa0lo[8*q], a01 = xa0hi[8*q];
            u32 a02 = xa0lo[8*q + 4], a03 = xa0hi[8*q + 4];
            u32 a10 = xa1lo[8*q], a11r = xa1hi[8*q];
            u32 a12r = xa1lo[8*q + 4], a13 = xa1hi[8*q + 4];
            #pragma unroll
            for (int t = 0; t < 8; t++){
                uint2 bb = bf1[(q*8 + t)*32 + lane];
                mma16(d1[0][t], a00, a01, a02, a03, bb.x, bb.y);
                mma16(d1[1][t], a10, a11r, a12r, a13, bb.x, bb.y);
            }
        }
    }
    __syncwarp();   // all xh reads done before H overlay writes

    // ---------------- layer 1 scores + spill H rows (f32, stride 68) ------------
    #pragma unroll
    for (int bi = 0; bi < 2; bi++){
        float s1lo = 0.f, s2lo = 0.f, s1hi = 0.f, s2hi = 0.f;
        const float4* a1f = (const float4*)(sm + A1F_OFF);
        #pragma unroll
        for (int t = 0; t < 8; t++){
            float4 av = a1f[t*4 + tig];
            s1lo += d1[bi][t].x*av.x + d1[bi][t].y*av.y;
            s2lo += d1[bi][t].x*av.z + d1[bi][t].y*av.w;
            s1hi += d1[bi][t].z*av.x + d1[bi][t].w*av.y;
            s2hi += d1[bi][t].z*av.z + d1[bi][t].w*av.w;
        }
        s1lo += __shfl_xor_sync(0xffffffffu, s1lo, 1); s1lo += __shfl_xor_sync(0xffffffffu, s1lo, 2);
        s2lo += __shfl_xor_sync(0xffffffffu, s2lo, 1); s2lo += __shfl_xor_sync(0xffffffffu, s2lo, 2);
        s1hi += __shfl_xor_sync(0xffffffffu, s1hi, 1); s1hi += __shfl_xor_sync(0xffffffffu, s1hi, 2);
        s2hi += __shfl_xor_sync(0xffffffffu, s2hi, 1); s2hi += __shfl_xor_sync(0xffffffffu, s2hi, 2);

        float2* sb = (float2*)(ws + 1360) + bi*10;
        if (tig == 0){
            sb[gid] = make_float2(s1lo, s2lo);
            if (hi_ok) sb[8 + gid] = make_float2(s1hi, s2hi);
        }
        float* hb = ws + bi*680;   // f32, stride 68
        #pragma unroll
        for (int t = 0; t < 8; t++){
            int col = 8*t + 2*tig;
            *(float2*)(hb + gid*68 + col) = make_float2(d1[bi][t].x, d1[bi][t].y);
            if (hi_ok)
                *(float2*)(hb + (gid+8)*68 + col) = make_float2(d1[bi][t].z, d1[bi][t].w);
        }
    }
    __syncwarp();

    // ---------------- merged layer 1 softmax (20 lanes, both batches) -----------
    {
        int bb_ = lane / 10, r = lane - 10*bb_;
        int g = r / 5, j = r - 5*g;
        if (lane < 20){
            const float2* sb = (const float2*)(ws + 1360) + bb_*10;
            float* abuf = ws + 1440 + bb_*64;
            float t2j = sb[g*5 + j].y;
            float ex[5], cs = 0.f;
            #pragma unroll
            for (int i = 0; i < 5; i++){
                float e = sb[g*5 + i].x + t2j;
                e = (e > 0.f) ? e : ALPHA*e;
                ex[i] = __expf(e);
                cs += ex[i];
            }
            float rc = __fdividef(1.f, cs);
            #pragma unroll
            for (int i = 0; i < 5; i++) abuf[g*32 + i*5 + j] = ex[i]*rc;
        }
    }
    __syncwarp();

    // ---------------- apply1 + BN1 + ReLU -> h2 fp16 (stride 36) ----------------
    #pragma unroll
    for (int bi = 0; bi < 2; bi++){
        const float* hb = ws + bi*680;
        const float* abuf = ws + 1440 + bi*64;
        float Ox[2][5], Oy[2][5];
        #pragma unroll
        for (int inp = 0; inp < 2; inp++)
            #pragma unroll
            for (int i = 0; i < 5; i++){ Ox[inp][i] = 0.f; Oy[inp][i] = 0.f; }
        #pragma unroll
        for (int inp = 0; inp < 2; inp++)
            #pragma unroll
            for (int j = 0; j < 5; j++){
                float2 Hp = *(const float2*)(hb + (inp*5 + j)*68 + 2*lane);
                #pragma unroll
                for (int i = 0; i < 5; i++){
                    float a = abuf[inp*32 + i*5 + j];
                    Ox[inp][i] += a * Hp.x;
                    Oy[inp][i] += a * Hp.y;
                }
            }
        __syncwarp();   // H reads complete before fp16 overlay
        u32* h2 = (u32*)(ws + bi*680);   // fp16x2, stride 36 u32
        #pragma unroll
        for (int inp = 0; inp < 2; inp++)
            #pragma unroll
            for (int n = 0; n < 5; n++){
                float sc = sm[SC1_OFF+n], sh = sm[SH1_OFF+n];
                float v0 = fmaxf(0.f, Ox[inp][n]*sc + sh);
                float v1 = fmaxf(0.f, Oy[inp][n]*sc + sh);
                h2[(inp*5 + n)*36 + lane] = pkh(v0, v1);
            }
        __syncwarp();
    }

    // ---------------- layer 2 MMA: K=64 in 4 k16-steps, N=32 in 4 tiles ---------
    float4 d2[2][4];
    #pragma unroll
    for (int bi = 0; bi < 2; bi++)
        #pragma unroll
        for (int t = 0; t < 4; t++) d2[bi][t] = make_float4(0.f, 0.f, 0.f, 0.f);
    {
        const int hi_row2 = hi_ok ? (gid+8)*36 : 0;
        const u32* ha0lo = (const u32*)ws + gid*36 + tig;
        const u32* ha0hi = (const u32*)ws + hi_row2 + tig;
        const u32* ha1lo = ha0lo + 680;
        const u32* ha1hi = ha0hi + 680;
        const uint2* bf2 = (const uint2*)(sm + BF2_OFF);
        #pragma unroll
        for (int q = 0; q < 4; q++){
            u32 a00 = ha0lo[8*q], a01 = ha0hi[8*q];
            u32 a02 = ha0lo[8*q + 4], a03 = ha0hi[8*q + 4];
            u32 a10 = ha1lo[8*q], a11r = ha1hi[8*q];
            u32 a12r = ha1lo[8*q + 4], a13 = ha1hi[8*q + 4];
            #pragma unroll
            for (int t = 0; t < 4; t++){
                uint2 bb = bf2[(q*4 + t)*32 + lane];
                mma16(d2[0][t], a00, a01, a02, a03, bb.x, bb.y);
                mma16(d2[1][t], a10, a11r, a12r, a13, bb.x, bb.y);
            }
        }
    }
    __syncwarp();   // h2 reads done before hh overlay

    // ---------------- layer 2 scores + spill hh rows (f32, stride 34) -----------
    #pragma unroll
    for (int bi = 0; bi < 2; bi++){
        float ulo = 0.f, wlo = 0.f, uhi = 0.f, whi = 0.f;
        const float4* a2f = (const float4*)(sm + A2F_OFF);
        #pragma unroll
        for (int t = 0; t < 4; t++){
            float4 av = a2f[t*4 + tig];
            ulo += d2[bi][t].x*av.x + d2[bi][t].y*av.y;
            wlo += d2[bi][t].x*av.z + d2[bi][t].y*av.w;
            uhi += d2[bi][t].z*av.x + d2[bi][t].w*av.y;
            whi += d2[bi][t].z*av.z + d2[bi][t].w*av.w;
        }
        ulo += __shfl_xor_sync(0xffffffffu, ulo, 1); ulo += __shfl_xor_sync(0xffffffffu, ulo, 2);
        wlo += __shfl_xor_sync(0xffffffffu, wlo, 1); wlo += __shfl_xor_sync(0xffffffffu, wlo, 2);
        uhi += __shfl_xor_sync(0xffffffffu, uhi, 1); uhi += __shfl_xor_sync(0xffffffffu, uhi, 2);
        whi += __shfl_xor_sync(0xffffffffu, whi, 1); whi += __shfl_xor_sync(0xffffffffu, whi, 2);

        float2* sb2 = (float2*)(ws + 1400) + bi*10;
        if (tig == 0){
            sb2[gid] = make_float2(ulo, wlo);
            if (hi_ok) sb2[8 + gid] = make_float2(uhi, whi);
        }
        float* hhb = ws + bi*680;   // f32, stride 34
        #pragma unroll
        for (int t = 0; t < 4; t++){
            int col = 8*t + 2*tig;
            *(float2*)(hhb + gid*34 + col) = make_float2(d2[bi][t].x, d2[bi][t].y);
            if (hi_ok)
                *(float2*)(hhb + (gid+8)*34 + col) = make_float2(d2[bi][t].z, d2[bi][t].w);
        }
    }
    __syncwarp();

    // ---------------- merged layer 2 softmax (20 lanes) -------------------------
    {
        int bb_ = lane / 10, r = lane - 10*bb_;
        int g = r / 5, j = r - 5*g;
        if (lane < 20){
            const float2* sb2 = (const float2*)(ws + 1400) + bb_*10;
            float* abuf = ws + 1440 + bb_*64;
            float t2j = sb2[(1-g)*5 + j].y;
            float ex[5], cs = 0.f;
            #pragma unroll
            for (int i = 0; i < 5; i++){
                float e = sb2[g*5 + i].x + t2j;
                e = (e > 0.f) ? e : ALPHA*e;
                ex[i] = __expf(e);
                cs += ex[i];
            }
            float rc = __fdividef(1.f, cs);
            #pragma unroll
            for (int i = 0; i < 5; i++) abuf[g*32 + i*5 + j] = ex[i]*rc;
        }
    }
    __syncwarp();

    // ---------------- apply2 + BN2 + ReLU ----------------
    float y2[2][2][5];
    #pragma unroll
    for (int bi = 0; bi < 2; bi++){
        const float* hhb = ws + bi*680;
        const float* abuf = ws + 1440 + bi*64;
        float hv[2][5];
        #pragma unroll
        for (int g = 0; g < 2; g++)
            #pragma unroll
            for (int j = 0; j < 5; j++)
                hv[g][j] = hhb[(g*5 + j)*34 + lane];
        #pragma unroll
        for (int g = 0; g < 2; g++)
            #pragma unroll
            for (int i = 0; i < 5; i++){
                float o2 = 0.f;
                #pragma unroll
                for (int j = 0; j < 5; j++)
                    o2 += abuf[g*32 + i*5 + j] * hv[g][j];
                y2[bi][g][i] = fmaxf(0.f, o2*sm[SC2_OFF+i] + sm[SH2_OFF+i]);
            }
    }

    // ---------------- final linear (shared Wl loads, both batches) --------------
    u64 f2a[5], f2b[5];
    #pragma unroll
    for (int n = 0; n < 5; n++){
        f2a[n] = pk(y2[0][0][n], y2[0][1][n]);
        f2b[n] = pk(y2[1][0][n], y2[1][1][n]);
    }
    const u64* wlp = (const u64*)(sm + WL2_OFF);
    float res0 = 0.f, res1 = 0.f;
    #pragma unroll
    for (int k = 0; k < 13; k++){
        u64 aa = 0ull, ab = 0ull;
        #pragma unroll
        for (int n = 0; n < 5; n++){
            u64 w = wlp[k*160 + n*32 + lane];
            aa = ffma2(f2a[n], w, aa);
            ab = ffma2(f2b[n], w, ab);
        }
        float r0 = wsum(hsum(aa));
        float r1 = wsum(hsum(ab));
        if (lane == k){ res0 = r0 + sm[BL_OFF+k]; res1 = r1 + sm[BL_OFF+k]; }
    }
    if (lane < 13){
        out[(size_t)b0i*13 + lane] = res0;
        if (has_b1) out[(size_t)b1i*13 + lane] = res1;
    }
}

extern "C" void kernel_launch(void* const* d_in, const int* in_sizes, int n_in,
                              void* d_out, int out_size)
{
    const float* x   = (const float*)d_in[0];
    const float* Wt1 = (const float*)d_in[1];
    const float* a11 = (const float*)d_in[2];
    const float* a21 = (const float*)d_in[3];
    const float* g1  = (const float*)d_in[4];
    const float* b1  = (const float*)d_in[5];
    const float* m1  = (const float*)d_in[6];
    const float* v1  = (const float*)d_in[7];
    const float* Wt2 = (const float*)d_in[8];
    const float* a12 = (const float*)d_in[9];
    const float* a22 = (const float*)d_in[10];
    const float* g2  = (const float*)d_in[11];
    const float* b2  = (const float*)d_in[12];
    const float* m2  = (const float*)d_in[13];
    const float* v2  = (const float*)d_in[14];
    const float* Wl  = (const float*)d_in[15];
    const float* bl  = (const float*)d_in[16];

    int B = in_sizes[0] / 1250;
    size_t smem_bytes = (size_t)SMEM_FLOATS * sizeof(float);
    cudaFuncSetAttribute(gat_fused_kernel,
                         cudaFuncAttributeMaxDynamicSharedMemorySize, (int)smem_bytes);

    int batches_per_block = WARPS * 2;
    dim3 grid((B + batches_per_block - 1) / batches_per_block);
    gat_fused_kernel<<<grid, THREADS, smem_bytes>>>(
        x, Wt1, a11, a21, g1, b1, m1, v1,
        Wt2, a12, a22, g2, b2, m2, v2, Wl, bl,
        (float*)d_out, B);
}